// round 11
// baseline (speedup 1.0000x reference)
#include <cuda_runtime.h>
#include <cuda_bf16.h>

// Problem constants
#define BB 16
#define NN 25200
#define NC 80
#define STRIDE 85
#define KK 1024
#define MAXDET 1000
#define CONF_T 0.25f
#define IOU_T 0.45f
#define MAXWH 4096.0f

// ---------------- scratch (device globals; no allocations allowed) --------
__device__ unsigned int        g_key[BB * NN];          // masked conf bits (0 = invalid)
__device__ unsigned char       g_cls[BB * NN];          // argmax class
__device__ int                 g_cidx[BB * KK];         // candidate anchor index
__device__ float               g_cconf[BB * KK];        // candidate conf (-1 invalid)
__device__ float               g_ccls[BB * KK];         // candidate class (float)
__device__ float4              g_cbox[BB * KK];         // raw xyxy
__device__ float4              g_cobox[BB * KK];        // offset xyxy
__device__ float               g_carea[BB * KK];        // area of offset box
__device__ unsigned long long  g_mask[BB * KK * (KK/64)]; // IoU > thr bitmask
__device__ int                 g_nvalid[BB];

// ---------------- K1: conf/cls per anchor (one warp per anchor) ----------
__global__ void score_kernel(const float* __restrict__ pred) {
    int gw   = (blockIdx.x * blockDim.x + threadIdx.x) >> 5;
    int lane = threadIdx.x & 31;
    if (gw >= BB * NN) return;
    const float* p = pred + (size_t)gw * STRIDE;
    float obj = p[4];                       // broadcast within warp
    float best = -1.0f; int bi = 0x7fffffff;
    #pragma unroll
    for (int c = lane; c < NC; c += 32) {
        float v = __fmul_rn(p[5 + c], obj); // scores = cls * obj, then max (matches ref order)
        if (v > best) { best = v; bi = c; } // strict > keeps first occurrence
    }
    #pragma unroll
    for (int off = 16; off > 0; off >>= 1) {
        float ov = __shfl_down_sync(0xffffffffu, best, off);
        int   oi = __shfl_down_sync(0xffffffffu, bi,   off);
        if (ov > best || (ov == best && oi < bi)) { best = ov; bi = oi; }
    }
    if (lane == 0) {
        unsigned key = (best > CONF_T) ? __float_as_uint(best) : 0u;
        g_key[gw] = key;
        g_cls[gw] = (unsigned char)bi;
    }
}

// ---------------- K2: per-image radix select + bitonic sort top-1024 -----
__global__ void __launch_bounds__(1024) select_sort_kernel() {
    int b = blockIdx.x, tid = threadIdx.x;
    const unsigned* __restrict__ key = g_key + b * NN;

    __shared__ unsigned           s_hist[256];
    __shared__ unsigned long long s_pairs[2048];
    __shared__ unsigned           s_prefix, s_mask;
    __shared__ int                s_want, s_cnt;

    if (tid == 0) { s_prefix = 0u; s_mask = 0u; s_want = KK; s_cnt = 0; }

    for (int pass = 0; pass < 4; ++pass) {
        int shift = 24 - pass * 8;
        if (tid < 256) s_hist[tid] = 0u;
        __syncthreads();
        unsigned pre = s_prefix, msk = s_mask;
        for (int a = tid; a < NN; a += 1024) {
            unsigned k = key[a];
            if ((k & msk) == pre) atomicAdd(&s_hist[(k >> shift) & 255u], 1u);
        }
        __syncthreads();
        if (tid == 0) {
            int want = s_want, cum = 0, chosen = -1, above = 0;
            for (int d = 255; d >= 0; --d) {
                int h = (int)s_hist[d];
                if (cum + h >= want) { chosen = d; above = cum; break; }
                cum += h;
            }
            if (chosen < 0) { chosen = 0; above = cum - (int)s_hist[0]; }
            s_prefix = pre | ((unsigned)chosen << shift);
            s_mask   = msk | (255u << shift);
            s_want   = want - above;
        }
        __syncthreads();
    }
    unsigned T = s_prefix;

    // gather all valid keys >= T (count of strictly-greater < 1024; ties ~1)
    for (int a = tid; a < NN; a += 1024) {
        unsigned k = key[a];
        if (k != 0u && k >= T) {
            int p = atomicAdd(&s_cnt, 1);
            if (p < 2048)
                s_pairs[p] = ((unsigned long long)k << 32) |
                             (unsigned long long)(0xFFFFFFFFu - (unsigned)a);
        }
    }
    __syncthreads();
    int cnt = min(s_cnt, 2048);
    for (int i = tid; i < 2048; i += 1024)
        if (i >= cnt) s_pairs[i] = 0ull;

    // bitonic sort 2048, descending (key desc, idx asc via ~idx)
    for (int k2 = 2; k2 <= 2048; k2 <<= 1) {
        for (int j = k2 >> 1; j > 0; j >>= 1) {
            __syncthreads();
            for (int idx = tid; idx < 2048; idx += 1024) {
                int ixj = idx ^ j;
                if (ixj > idx) {
                    bool dir = ((idx & k2) == 0);
                    unsigned long long A = s_pairs[idx], Bv = s_pairs[ixj];
                    if ((A < Bv) == dir) { s_pairs[idx] = Bv; s_pairs[ixj] = A; }
                }
            }
        }
    }
    __syncthreads();

    unsigned long long pr = s_pairs[tid];
    unsigned kk = (unsigned)(pr >> 32);
    unsigned ai = 0xFFFFFFFFu - (unsigned)(pr & 0xFFFFFFFFull);
    g_cidx [b * KK + tid] = kk ? (int)ai : 0;
    g_cconf[b * KK + tid] = kk ? __uint_as_float(kk) : -1.0f;
    if (tid == 0) g_nvalid[b] = min(cnt, KK);
}

// ---------------- K3: gather candidate boxes / offsets / areas -----------
__global__ void __launch_bounds__(1024) cand_kernel(const float* __restrict__ pred) {
    int b = blockIdx.x, tid = threadIdx.x;
    int t = b * KK + tid;
    float conf = g_cconf[t];
    bool  valid = conf > 0.0f;
    int   idx  = g_cidx[t];
    float cx = 0.f, cy = 0.f, w = 0.f, h = 0.f, cls = 0.f;
    if (valid) {
        const float* p = pred + ((size_t)b * NN + (size_t)idx) * STRIDE;
        cx = p[0]; cy = p[1]; w = p[2]; h = p[3];
        cls = (float)g_cls[b * NN + idx];
    }
    float hw = __fmul_rn(w, 0.5f), hh = __fmul_rn(h, 0.5f);
    float x1 = __fsub_rn(cx, hw), y1 = __fsub_rn(cy, hh);
    float x2 = __fadd_rn(cx, hw), y2 = __fadd_rn(cy, hh);
    float off = __fmul_rn(cls, MAXWH);
    float ox1 = __fadd_rn(x1, off), oy1 = __fadd_rn(y1, off);
    float ox2 = __fadd_rn(x2, off), oy2 = __fadd_rn(y2, off);
    g_cbox [t] = make_float4(x1, y1, x2, y2);
    g_cobox[t] = make_float4(ox1, oy1, ox2, oy2);
    g_carea[t] = __fmul_rn(__fsub_rn(ox2, ox1), __fsub_rn(oy2, oy1));
    g_ccls [t] = cls;
}

// ---------------- K4: pairwise IoU bitmask (64x64 tiles) -----------------
__global__ void iou_kernel() {
    int bid = blockIdx.x;                // b*256 + rb*16 + cb
    int cb = bid & 15, rb = (bid >> 4) & 15, b = bid >> 8;
    int tj = threadIdx.x;                // 0..63

    __shared__ float4 s_box[64];
    __shared__ float  s_area[64];
    int c = cb * 64 + tj;
    s_box[tj]  = g_cobox[b * KK + c];
    s_area[tj] = g_carea[b * KK + c];
    __syncthreads();

    int r = rb * 64 + tj;
    float4 rbx = g_cobox[b * KK + r];
    float  ra  = g_carea[b * KK + r];
    unsigned long long bits = 0ull;
    #pragma unroll 4
    for (int j = 0; j < 64; ++j) {
        float4 o = s_box[j];
        float ix1 = fmaxf(rbx.x, o.x), iy1 = fmaxf(rbx.y, o.y);
        float ix2 = fminf(rbx.z, o.z), iy2 = fminf(rbx.w, o.w);
        float iw = fmaxf(__fsub_rn(ix2, ix1), 0.0f);
        float ih = fmaxf(__fsub_rn(iy2, iy1), 0.0f);
        float inter = __fmul_rn(iw, ih);
        float denom = __fadd_rn(__fsub_rn(__fadd_rn(ra, s_area[j]), inter), 1e-9f);
        float iou = __fdiv_rn(inter, denom);
        if (iou > IOU_T) bits |= (1ull << j);
    }
    g_mask[((size_t)(b * KK + r)) * (KK/64) + cb] = bits;
}

// ---------------- K5: blocked greedy suppression scan + output -----------
__global__ void __launch_bounds__(1024) scan_output_kernel(float* __restrict__ out) {
    int b = blockIdx.x, tid = threadIdx.x;
    const int NW = KK / 64;              // 16 mask words

    __shared__ unsigned long long s_remv[16];
    __shared__ unsigned long long s_tile[64];
    __shared__ unsigned long long s_keptAll[16];
    __shared__ short              s_outidx[MAXDET];

    int nvalid = g_nvalid[b];
    if (tid < 16) { s_remv[tid] = 0ull; s_keptAll[tid] = 0ull; }
    __syncthreads();

    for (int t = 0; t < 16; ++t) {
        if (tid < 64)
            s_tile[tid] = g_mask[((size_t)(b * KK + t * 64 + tid)) * NW + t];
        __syncthreads();
        if (tid == 0) {
            unsigned long long rem = s_remv[t], kept = 0ull;
            int base = t * 64;
            int lim = nvalid - base; if (lim > 64) lim = 64; if (lim < 0) lim = 0;
            for (int i = 0; i < lim; ++i) {
                if (!((rem >> i) & 1ull)) {
                    kept |= (1ull << i);
                    rem  |= s_tile[i];
                }
            }
            s_keptAll[t] = kept;
        }
        __syncthreads();
        unsigned long long kept = s_keptAll[t];
        int i = tid >> 4, w = tid & 15;
        if (w > t && ((kept >> i) & 1ull))
            atomicOr(&s_remv[w], g_mask[((size_t)(b * KK + t * 64 + i)) * NW + w]);
        __syncthreads();
    }

    // compaction: rank kept candidates (stable order = conf desc already)
    if (tid < MAXDET) s_outidx[tid] = -1;
    __syncthreads();
    {
        int r = tid, wr = r >> 6, br = r & 63;
        unsigned long long kw = s_keptAll[wr];
        if ((kw >> br) & 1ull) {
            int pos = 0;
            for (int w = 0; w < wr; ++w) pos += __popcll(s_keptAll[w]);
            pos += __popcll(kw & ((1ull << br) - 1ull));
            if (pos < MAXDET) s_outidx[pos] = (short)r;
        }
    }
    __syncthreads();

    float* outb = out + (size_t)b * MAXDET * 6;
    for (int row = tid; row < MAXDET; row += 1024) {
        int r = s_outidx[row];
        float v0, v1, v2, v3, v4, v5;
        if (r >= 0) {
            float4 bx = g_cbox[b * KK + r];
            v0 = bx.x; v1 = bx.y; v2 = bx.z; v3 = bx.w;
            v4 = g_cconf[b * KK + r];
            v5 = g_ccls [b * KK + r];
        } else {
            v0 = v1 = v2 = v3 = v4 = v5 = 0.0f;
        }
        float* o = outb + (size_t)row * 6;
        o[0] = v0; o[1] = v1; o[2] = v2; o[3] = v3; o[4] = v4; o[5] = v5;
    }
}

// ---------------- launch ---------------------------------------------------
extern "C" void kernel_launch(void* const* d_in, const int* in_sizes, int n_in,
                              void* d_out, int out_size) {
    const float* pred = (const float*)d_in[0];
    float* out = (float*)d_out;
    (void)in_sizes; (void)n_in; (void)out_size;

    // K1: one warp per anchor, 8 warps/block
    int nblocks1 = (BB * NN + 7) / 8;            // 50400
    score_kernel<<<nblocks1, 256>>>(pred);

    // K2: radix select + sort per image
    select_sort_kernel<<<BB, 1024>>>();

    // K3: candidate data
    cand_kernel<<<BB, 1024>>>(pred);

    // K4: IoU mask tiles
    iou_kernel<<<BB * 256, 64>>>();

    // K5: suppression scan + output
    scan_output_kernel<<<BB, 1024>>>(out);
}

// round 12
// speedup vs baseline: 1.0579x; 1.0579x over previous
#include <cuda_runtime.h>
#include <cuda_bf16.h>

// Problem constants
#define BB 16
#define NN 25200
#define NC 80
#define STRIDE 85
#define KK 1024
#define MAXDET 1000
#define CONF_T 0.25f
#define IOU_T 0.45f
#define MAXWH 4096.0f

#define NBIN 2048
#define KEY_BASE 0x3E800001u   // smallest float bits > 0.25f
#define GBUF 4096

// ---------------- scratch (device globals; no allocations allowed) --------
__device__ unsigned int        g_key[BB * NN];          // masked conf bits (0 = invalid)
__device__ unsigned char       g_cls[BB * NN];          // argmax class
__device__ int                 g_hist[BB * NBIN];       // per-image key histogram
__device__ float               g_cconf[BB * KK];        // candidate conf (-1 invalid)
__device__ float               g_ccls[BB * KK];         // candidate class (float)
__device__ float4              g_cbox[BB * KK];         // raw xyxy
__device__ float4              g_cobox[BB * KK];        // offset xyxy
__device__ float               g_carea[BB * KK];        // area of offset box
__device__ unsigned long long  g_mask[BB * KK * (KK/64)]; // IoU>thr bitmask (upper block-tri valid)
__device__ int                 g_nvalid[BB];

// ---------------- K0: zero the histograms ---------------------------------
__global__ void zero_hist_kernel() {
    int i = blockIdx.x * blockDim.x + threadIdx.x;
    if (i < BB * NBIN) g_hist[i] = 0;
}

// ---------------- K1: conf/cls per anchor (one warp per anchor) + hist ----
__global__ void score_kernel(const float* __restrict__ pred) {
    int gw   = (blockIdx.x * blockDim.x + threadIdx.x) >> 5;
    int lane = threadIdx.x & 31;
    if (gw >= BB * NN) return;
    const float* p = pred + (size_t)gw * STRIDE;
    float obj = p[4];
    float best = -1.0f; int bi = 0x7fffffff;
    #pragma unroll
    for (int c = lane; c < NC; c += 32) {
        float v = __fmul_rn(p[5 + c], obj); // scores = cls*obj then max (ref order)
        if (v > best) { best = v; bi = c; } // strict > keeps first occurrence
    }
    #pragma unroll
    for (int off = 16; off > 0; off >>= 1) {
        float ov = __shfl_down_sync(0xffffffffu, best, off);
        int   oi = __shfl_down_sync(0xffffffffu, bi,   off);
        if (ov > best || (ov == best && oi < bi)) { best = ov; bi = oi; }
    }
    if (lane == 0) {
        unsigned key = (best > CONF_T) ? __float_as_uint(best) : 0u;
        g_key[gw] = key;
        g_cls[gw] = (unsigned char)bi;
        if (key) {
            unsigned bin = (key - KEY_BASE) >> 13;
            if (bin > (NBIN - 1)) bin = NBIN - 1;
            atomicAdd(&g_hist[(gw / NN) * NBIN + bin], 1);
        }
    }
}

// ---------------- K2: threshold from hist + gather + sort + candidate data -
__global__ void __launch_bounds__(1024) select_sort_kernel(const float* __restrict__ pred) {
    int b = blockIdx.x, tid = threadIdx.x;
    const unsigned* __restrict__ key = g_key + b * NN;

    __shared__ int                s_hist[NBIN];
    __shared__ unsigned long long s_pairs[GBUF];
    __shared__ unsigned           s_T;
    __shared__ int                s_cnt;

    // copy histogram to shared
    for (int i = tid; i < NBIN; i += 1024) s_hist[i] = g_hist[b * NBIN + i];
    if (tid == 0) s_cnt = 0;
    __syncthreads();

    // find threshold bin: largest d with suffix count >= KK (early exit, ~90 iters)
    if (tid == 0) {
        int cum = 0, dstar = 0;
        for (int d = NBIN - 1; d >= 0; --d) {
            cum += s_hist[d];
            if (cum >= KK) { dstar = d; break; }
        }
        s_T = KEY_BASE + ((unsigned)dstar << 13);
    }
    __syncthreads();
    unsigned T = s_T;

    // gather all keys >= T
    for (int a = tid; a < NN; a += 1024) {
        unsigned k = key[a];
        if (k >= T) {
            int p = atomicAdd(&s_cnt, 1);
            if (p < GBUF)
                s_pairs[p] = ((unsigned long long)k << 32) |
                             (unsigned long long)(0xFFFFFFFFu - (unsigned)a);
        }
    }
    __syncthreads();
    int cnt = min(s_cnt, GBUF);
    for (int i = tid; i < GBUF; i += 1024)
        if (i >= cnt) s_pairs[i] = 0ull;

    // bitonic sort GBUF=4096, descending (key desc, idx asc via ~idx)
    for (int k2 = 2; k2 <= GBUF; k2 <<= 1) {
        for (int j = k2 >> 1; j > 0; j >>= 1) {
            __syncthreads();
            for (int idx = tid; idx < GBUF; idx += 1024) {
                int ixj = idx ^ j;
                if (ixj > idx) {
                    bool dir = ((idx & k2) == 0);
                    unsigned long long A = s_pairs[idx], Bv = s_pairs[ixj];
                    if ((A < Bv) == dir) { s_pairs[idx] = Bv; s_pairs[ixj] = A; }
                }
            }
        }
    }
    __syncthreads();

    // candidate data for top-1024 (fused old cand_kernel)
    unsigned long long pr = s_pairs[tid];
    unsigned kk = (unsigned)(pr >> 32);
    unsigned ai = 0xFFFFFFFFu - (unsigned)(pr & 0xFFFFFFFFull);
    int t = b * KK + tid;
    float cx = 0.f, cy = 0.f, w = 0.f, h = 0.f, cls = 0.f;
    if (kk) {
        const float* p = pred + ((size_t)b * NN + (size_t)ai) * STRIDE;
        cx = p[0]; cy = p[1]; w = p[2]; h = p[3];
        cls = (float)g_cls[b * NN + ai];
    }
    float hw = __fmul_rn(w, 0.5f), hh = __fmul_rn(h, 0.5f);
    float x1 = __fsub_rn(cx, hw), y1 = __fsub_rn(cy, hh);
    float x2 = __fadd_rn(cx, hw), y2 = __fadd_rn(cy, hh);
    float off = __fmul_rn(cls, MAXWH);
    float ox1 = __fadd_rn(x1, off), oy1 = __fadd_rn(y1, off);
    float ox2 = __fadd_rn(x2, off), oy2 = __fadd_rn(y2, off);
    g_cbox [t] = make_float4(x1, y1, x2, y2);
    g_cobox[t] = make_float4(ox1, oy1, ox2, oy2);
    g_carea[t] = __fmul_rn(__fsub_rn(ox2, ox1), __fsub_rn(oy2, oy1));
    g_ccls [t] = cls;
    g_cconf[t] = kk ? __uint_as_float(kk) : -1.0f;
    if (tid == 0) g_nvalid[b] = min(cnt, KK);
}

// ---------------- K3: pairwise IoU bitmask, upper block-triangle, ballots --
// grid = BB * 136 blocks of 256 threads; one block per 64x64 tile (cb >= rb)
__global__ void __launch_bounds__(256) iou_kernel() {
    int m = blockIdx.x % 136;
    int b = blockIdx.x / 136;
    // decode m -> (rb, cb) with cb >= rb   (row-major over upper triangle)
    int rb = 0, rem = m;
    #pragma unroll
    for (int i = 0; i < 16; ++i) {
        if (rem >= 16 - rb) { rem -= 16 - rb; rb++; } else break;
    }
    int cb = rb + rem;

    int tid  = threadIdx.x;
    int warp = tid >> 5, lane = tid & 31;

    __shared__ float4 s_box[64];
    __shared__ float  s_area[64];
    if (tid < 64) {
        int c = cb * 64 + tid;
        s_box[tid]  = g_cobox[b * KK + c];
        s_area[tid] = g_carea[b * KK + c];
    }
    __syncthreads();

    #pragma unroll
    for (int k = 0; k < 8; ++k) {
        int row = warp * 8 + k;                 // 0..63 within tile
        int r = rb * 64 + row;
        float4 rbx = g_cobox[b * KK + r];
        float  ra  = g_carea[b * KK + r];

        // column = lane and lane+32
        float4 o0 = s_box[lane];
        float4 o1 = s_box[lane + 32];
        float a0 = s_area[lane], a1 = s_area[lane + 32];

        float ix1 = fmaxf(rbx.x, o0.x), iy1 = fmaxf(rbx.y, o0.y);
        float ix2 = fminf(rbx.z, o0.z), iy2 = fminf(rbx.w, o0.w);
        float iw = fmaxf(__fsub_rn(ix2, ix1), 0.0f);
        float ih = fmaxf(__fsub_rn(iy2, iy1), 0.0f);
        float inter0 = __fmul_rn(iw, ih);
        float den0 = __fadd_rn(__fsub_rn(__fadd_rn(ra, a0), inter0), 1e-9f);
        bool hit0 = __fdiv_rn(inter0, den0) > IOU_T;

        ix1 = fmaxf(rbx.x, o1.x); iy1 = fmaxf(rbx.y, o1.y);
        ix2 = fminf(rbx.z, o1.z); iy2 = fminf(rbx.w, o1.w);
        iw = fmaxf(__fsub_rn(ix2, ix1), 0.0f);
        ih = fmaxf(__fsub_rn(iy2, iy1), 0.0f);
        float inter1 = __fmul_rn(iw, ih);
        float den1 = __fadd_rn(__fsub_rn(__fadd_rn(ra, a1), inter1), 1e-9f);
        bool hit1 = __fdiv_rn(inter1, den1) > IOU_T;

        unsigned lo = __ballot_sync(0xffffffffu, hit0);
        unsigned hi = __ballot_sync(0xffffffffu, hit1);
        if (lane == 0)
            g_mask[((size_t)(b * KK + r)) * (KK/64) + cb] =
                ((unsigned long long)hi << 32) | (unsigned long long)lo;
    }
}

// ---------------- K4: blocked greedy suppression scan + output -----------
__global__ void __launch_bounds__(1024) scan_output_kernel(float* __restrict__ out) {
    int b = blockIdx.x, tid = threadIdx.x;
    const int NW = KK / 64;

    __shared__ unsigned long long s_remv[16];
    __shared__ unsigned long long s_tile[64];
    __shared__ unsigned long long s_keptAll[16];
    __shared__ short              s_outidx[MAXDET];

    int nvalid = g_nvalid[b];
    if (tid < 16) { s_remv[tid] = 0ull; s_keptAll[tid] = 0ull; }
    __syncthreads();

    for (int t = 0; t < 16; ++t) {
        if (tid < 64)
            s_tile[tid] = g_mask[((size_t)(b * KK + t * 64 + tid)) * NW + t];
        __syncthreads();
        if (tid == 0) {
            unsigned long long rem = s_remv[t], kept = 0ull;
            int base = t * 64;
            int lim = nvalid - base; if (lim > 64) lim = 64; if (lim < 0) lim = 0;
            for (int i = 0; i < lim; ++i) {
                if (!((rem >> i) & 1ull)) {
                    kept |= (1ull << i);
                    rem  |= s_tile[i];
                }
            }
            s_keptAll[t] = kept;
        }
        __syncthreads();
        unsigned long long kept = s_keptAll[t];
        int i = tid >> 4, w = tid & 15;
        if (w > t && ((kept >> i) & 1ull))
            atomicOr(&s_remv[w], g_mask[((size_t)(b * KK + t * 64 + i)) * NW + w]);
        __syncthreads();
    }

    // compaction: rank kept candidates (stable order = conf desc already)
    if (tid < MAXDET) s_outidx[tid] = -1;
    __syncthreads();
    {
        int r = tid, wr = r >> 6, br = r & 63;
        unsigned long long kw = s_keptAll[wr];
        if ((kw >> br) & 1ull) {
            int pos = 0;
            for (int w = 0; w < wr; ++w) pos += __popcll(s_keptAll[w]);
            pos += __popcll(kw & ((1ull << br) - 1ull));
            if (pos < MAXDET) s_outidx[pos] = (short)r;
        }
    }
    __syncthreads();

    float* outb = out + (size_t)b * MAXDET * 6;
    for (int row = tid; row < MAXDET; row += 1024) {
        int r = s_outidx[row];
        float v0, v1, v2, v3, v4, v5;
        if (r >= 0) {
            float4 bx = g_cbox[b * KK + r];
            v0 = bx.x; v1 = bx.y; v2 = bx.z; v3 = bx.w;
            v4 = g_cconf[b * KK + r];
            v5 = g_ccls [b * KK + r];
        } else {
            v0 = v1 = v2 = v3 = v4 = v5 = 0.0f;
        }
        float* o = outb + (size_t)row * 6;
        o[0] = v0; o[1] = v1; o[2] = v2; o[3] = v3; o[4] = v4; o[5] = v5;
    }
}

// ---------------- launch ---------------------------------------------------
extern "C" void kernel_launch(void* const* d_in, const int* in_sizes, int n_in,
                              void* d_out, int out_size) {
    const float* pred = (const float*)d_in[0];
    float* out = (float*)d_out;
    (void)in_sizes; (void)n_in; (void)out_size;

    zero_hist_kernel<<<(BB * NBIN + 1023) / 1024, 1024>>>();

    // K1: one warp per anchor, 8 warps/block
    int nblocks1 = (BB * NN + 7) / 8;            // 50400
    score_kernel<<<nblocks1, 256>>>(pred);

    // K2: hist threshold + gather + bitonic sort + candidate data
    select_sort_kernel<<<BB, 1024>>>(pred);

    // K3: IoU mask tiles (upper block triangle)
    iou_kernel<<<BB * 136, 256>>>();

    // K4: suppression scan + output
    scan_output_kernel<<<BB, 1024>>>(out);
}

// round 13
// speedup vs baseline: 1.0720x; 1.0134x over previous
#include <cuda_runtime.h>
#include <cuda_bf16.h>

// Problem constants
#define BB 16
#define NN 25200
#define NC 80
#define STRIDE 85
#define KK 1024
#define MAXDET 1000
#define CONF_T 0.25f
#define IOU_T 0.45f
#define MAXWH 4096.0f

#define NBIN 2048
#define KEY_BASE 0x3E800001u   // smallest float bits > 0.25f
#define GBUF 4096

// ---------------- scratch (device globals; no allocations allowed) --------
__device__ unsigned int        g_key[BB * NN];          // masked conf bits (0 = invalid)
__device__ unsigned char       g_cls[BB * NN];          // argmax class
__device__ int                 g_hist[BB * NBIN];       // per-image key histogram
__device__ float               g_cconf[BB * KK];        // candidate conf (-1 invalid)
__device__ float               g_ccls[BB * KK];         // candidate class (float)
__device__ float4              g_cbox[BB * KK];         // raw xyxy
__device__ float4              g_cobox[BB * KK];        // offset xyxy
__device__ float               g_carea[BB * KK];        // area of offset box
__device__ unsigned long long  g_mask[BB * KK * (KK/64)]; // IoU>thr bitmask (upper block-tri valid)
__device__ int                 g_nvalid[BB];

// ---------------- K0: zero the histograms ---------------------------------
__global__ void zero_hist_kernel() {
    int i = blockIdx.x * blockDim.x + threadIdx.x;
    if (i < BB * NBIN) g_hist[i] = 0;
}

// ---------------- K1: conf/cls per anchor (one warp per anchor) + hist ----
__global__ void score_kernel(const float* __restrict__ pred) {
    int gw   = (blockIdx.x * blockDim.x + threadIdx.x) >> 5;
    int lane = threadIdx.x & 31;
    if (gw >= BB * NN) return;
    const float* p = pred + (size_t)gw * STRIDE;
    float obj = p[4];
    float best = -1.0f; int bi = 0x7fffffff;
    #pragma unroll
    for (int c = lane; c < NC; c += 32) {
        float v = __fmul_rn(p[5 + c], obj); // scores = cls*obj then max (ref order)
        if (v > best) { best = v; bi = c; } // strict > keeps first occurrence
    }
    #pragma unroll
    for (int off = 16; off > 0; off >>= 1) {
        float ov = __shfl_down_sync(0xffffffffu, best, off);
        int   oi = __shfl_down_sync(0xffffffffu, bi,   off);
        if (ov > best || (ov == best && oi < bi)) { best = ov; bi = oi; }
    }
    if (lane == 0) {
        unsigned key = (best > CONF_T) ? __float_as_uint(best) : 0u;
        g_key[gw] = key;
        g_cls[gw] = (unsigned char)bi;
        if (key) {
            unsigned bin = (key - KEY_BASE) >> 13;
            if (bin > (NBIN - 1)) bin = NBIN - 1;
            atomicAdd(&g_hist[(gw / NN) * NBIN + bin], 1);
        }
    }
}

// ---------------- K2: threshold from hist + gather + sort + candidate data -
__global__ void __launch_bounds__(1024) select_sort_kernel(const float* __restrict__ pred) {
    int b = blockIdx.x, tid = threadIdx.x;
    const unsigned* __restrict__ key = g_key + b * NN;

    __shared__ int                s_hist[NBIN];
    __shared__ unsigned long long s_pairs[GBUF];
    __shared__ unsigned           s_T;
    __shared__ int                s_cnt;

    // copy histogram to shared
    for (int i = tid; i < NBIN; i += 1024) s_hist[i] = g_hist[b * NBIN + i];
    if (tid == 0) s_cnt = 0;
    __syncthreads();

    // find threshold bin: largest d with suffix count >= KK (early exit, ~90 iters)
    if (tid == 0) {
        int cum = 0, dstar = 0;
        for (int d = NBIN - 1; d >= 0; --d) {
            cum += s_hist[d];
            if (cum >= KK) { dstar = d; break; }
        }
        s_T = KEY_BASE + ((unsigned)dstar << 13);
    }
    __syncthreads();
    unsigned T = s_T;

    // gather all keys >= T
    for (int a = tid; a < NN; a += 1024) {
        unsigned k = key[a];
        if (k >= T) {
            int p = atomicAdd(&s_cnt, 1);
            if (p < GBUF)
                s_pairs[p] = ((unsigned long long)k << 32) |
                             (unsigned long long)(0xFFFFFFFFu - (unsigned)a);
        }
    }
    __syncthreads();
    int cnt = min(s_cnt, GBUF);
    for (int i = tid; i < GBUF; i += 1024)
        if (i >= cnt) s_pairs[i] = 0ull;

    // bitonic sort GBUF=4096, descending (key desc, idx asc via ~idx)
    for (int k2 = 2; k2 <= GBUF; k2 <<= 1) {
        for (int j = k2 >> 1; j > 0; j >>= 1) {
            __syncthreads();
            for (int idx = tid; idx < GBUF; idx += 1024) {
                int ixj = idx ^ j;
                if (ixj > idx) {
                    bool dir = ((idx & k2) == 0);
                    unsigned long long A = s_pairs[idx], Bv = s_pairs[ixj];
                    if ((A < Bv) == dir) { s_pairs[idx] = Bv; s_pairs[ixj] = A; }
                }
            }
        }
    }
    __syncthreads();

    // candidate data for top-1024 (fused old cand_kernel)
    unsigned long long pr = s_pairs[tid];
    unsigned kk = (unsigned)(pr >> 32);
    unsigned ai = 0xFFFFFFFFu - (unsigned)(pr & 0xFFFFFFFFull);
    int t = b * KK + tid;
    float cx = 0.f, cy = 0.f, w = 0.f, h = 0.f, cls = 0.f;
    if (kk) {
        const float* p = pred + ((size_t)b * NN + (size_t)ai) * STRIDE;
        cx = p[0]; cy = p[1]; w = p[2]; h = p[3];
        cls = (float)g_cls[b * NN + ai];
    }
    float hw = __fmul_rn(w, 0.5f), hh = __fmul_rn(h, 0.5f);
    float x1 = __fsub_rn(cx, hw), y1 = __fsub_rn(cy, hh);
    float x2 = __fadd_rn(cx, hw), y2 = __fadd_rn(cy, hh);
    float off = __fmul_rn(cls, MAXWH);
    float ox1 = __fadd_rn(x1, off), oy1 = __fadd_rn(y1, off);
    float ox2 = __fadd_rn(x2, off), oy2 = __fadd_rn(y2, off);
    g_cbox [t] = make_float4(x1, y1, x2, y2);
    g_cobox[t] = make_float4(ox1, oy1, ox2, oy2);
    g_carea[t] = __fmul_rn(__fsub_rn(ox2, ox1), __fsub_rn(oy2, oy1));
    g_ccls [t] = cls;
    g_cconf[t] = kk ? __uint_as_float(kk) : -1.0f;
    if (tid == 0) g_nvalid[b] = min(cnt, KK);
}

// ---------------- K3: pairwise IoU bitmask, upper block-triangle, ballots --
// grid = BB * 136 blocks of 256 threads; one block per 64x64 tile (cb >= rb)
__global__ void __launch_bounds__(256) iou_kernel() {
    int m = blockIdx.x % 136;
    int b = blockIdx.x / 136;
    // decode m -> (rb, cb) with cb >= rb   (row-major over upper triangle)
    int rb = 0, rem = m;
    #pragma unroll
    for (int i = 0; i < 16; ++i) {
        if (rem >= 16 - rb) { rem -= 16 - rb; rb++; } else break;
    }
    int cb = rb + rem;

    int tid  = threadIdx.x;
    int warp = tid >> 5, lane = tid & 31;

    __shared__ float4 s_box[64];
    __shared__ float  s_area[64];
    if (tid < 64) {
        int c = cb * 64 + tid;
        s_box[tid]  = g_cobox[b * KK + c];
        s_area[tid] = g_carea[b * KK + c];
    }
    __syncthreads();

    #pragma unroll
    for (int k = 0; k < 8; ++k) {
        int row = warp * 8 + k;                 // 0..63 within tile
        int r = rb * 64 + row;
        float4 rbx = g_cobox[b * KK + r];
        float  ra  = g_carea[b * KK + r];

        // column = lane and lane+32
        float4 o0 = s_box[lane];
        float4 o1 = s_box[lane + 32];
        float a0 = s_area[lane], a1 = s_area[lane + 32];

        float ix1 = fmaxf(rbx.x, o0.x), iy1 = fmaxf(rbx.y, o0.y);
        float ix2 = fminf(rbx.z, o0.z), iy2 = fminf(rbx.w, o0.w);
        float iw = fmaxf(__fsub_rn(ix2, ix1), 0.0f);
        float ih = fmaxf(__fsub_rn(iy2, iy1), 0.0f);
        float inter0 = __fmul_rn(iw, ih);
        float den0 = __fadd_rn(__fsub_rn(__fadd_rn(ra, a0), inter0), 1e-9f);
        bool hit0 = __fdiv_rn(inter0, den0) > IOU_T;

        ix1 = fmaxf(rbx.x, o1.x); iy1 = fmaxf(rbx.y, o1.y);
        ix2 = fminf(rbx.z, o1.z); iy2 = fminf(rbx.w, o1.w);
        iw = fmaxf(__fsub_rn(ix2, ix1), 0.0f);
        ih = fmaxf(__fsub_rn(iy2, iy1), 0.0f);
        float inter1 = __fmul_rn(iw, ih);
        float den1 = __fadd_rn(__fsub_rn(__fadd_rn(ra, a1), inter1), 1e-9f);
        bool hit1 = __fdiv_rn(inter1, den1) > IOU_T;

        unsigned lo = __ballot_sync(0xffffffffu, hit0);
        unsigned hi = __ballot_sync(0xffffffffu, hit1);
        if (lane == 0)
            g_mask[((size_t)(b * KK + r)) * (KK/64) + cb] =
                ((unsigned long long)hi << 32) | (unsigned long long)lo;
    }
}

// ---------------- K4: blocked greedy suppression scan + output -----------
__global__ void __launch_bounds__(1024) scan_output_kernel(float* __restrict__ out) {
    int b = blockIdx.x, tid = threadIdx.x;
    const int NW = KK / 64;

    __shared__ unsigned long long s_remv[16];
    __shared__ unsigned long long s_tile[64];
    __shared__ unsigned long long s_keptAll[16];
    __shared__ short              s_outidx[MAXDET];

    int nvalid = g_nvalid[b];
    if (tid < 16) { s_remv[tid] = 0ull; s_keptAll[tid] = 0ull; }
    __syncthreads();

    for (int t = 0; t < 16; ++t) {
        if (tid < 64)
            s_tile[tid] = g_mask[((size_t)(b * KK + t * 64 + tid)) * NW + t];
        __syncthreads();
        if (tid == 0) {
            unsigned long long rem = s_remv[t], kept = 0ull;
            int base = t * 64;
            int lim = nvalid - base; if (lim > 64) lim = 64; if (lim < 0) lim = 0;
            for (int i = 0; i < lim; ++i) {
                if (!((rem >> i) & 1ull)) {
                    kept |= (1ull << i);
                    rem  |= s_tile[i];
                }
            }
            s_keptAll[t] = kept;
        }
        __syncthreads();
        unsigned long long kept = s_keptAll[t];
        int i = tid >> 4, w = tid & 15;
        if (w > t && ((kept >> i) & 1ull))
            atomicOr(&s_remv[w], g_mask[((size_t)(b * KK + t * 64 + i)) * NW + w]);
        __syncthreads();
    }

    // compaction: rank kept candidates (stable order = conf desc already)
    if (tid < MAXDET) s_outidx[tid] = -1;
    __syncthreads();
    {
        int r = tid, wr = r >> 6, br = r & 63;
        unsigned long long kw = s_keptAll[wr];
        if ((kw >> br) & 1ull) {
            int pos = 0;
            for (int w = 0; w < wr; ++w) pos += __popcll(s_keptAll[w]);
            pos += __popcll(kw & ((1ull << br) - 1ull));
            if (pos < MAXDET) s_outidx[pos] = (short)r;
        }
    }
    __syncthreads();

    float* outb = out + (size_t)b * MAXDET * 6;
    for (int row = tid; row < MAXDET; row += 1024) {
        int r = s_outidx[row];
        float v0, v1, v2, v3, v4, v5;
        if (r >= 0) {
            float4 bx = g_cbox[b * KK + r];
            v0 = bx.x; v1 = bx.y; v2 = bx.z; v3 = bx.w;
            v4 = g_cconf[b * KK + r];
            v5 = g_ccls [b * KK + r];
        } else {
            v0 = v1 = v2 = v3 = v4 = v5 = 0.0f;
        }
        float* o = outb + (size_t)row * 6;
        o[0] = v0; o[1] = v1; o[2] = v2; o[3] = v3; o[4] = v4; o[5] = v5;
    }
}

// ---------------- launch ---------------------------------------------------
extern "C" void kernel_launch(void* const* d_in, const int* in_sizes, int n_in,
                              void* d_out, int out_size) {
    const float* pred = (const float*)d_in[0];
    float* out = (float*)d_out;
    (void)in_sizes; (void)n_in; (void)out_size;

    zero_hist_kernel<<<(BB * NBIN + 1023) / 1024, 1024>>>();

    // K1: one warp per anchor, 8 warps/block
    int nblocks1 = (BB * NN + 7) / 8;            // 50400
    score_kernel<<<nblocks1, 256>>>(pred);

    // K2: hist threshold + gather + bitonic sort + candidate data
    select_sort_kernel<<<BB, 1024>>>(pred);

    // K3: IoU mask tiles (upper block triangle)
    iou_kernel<<<BB * 136, 256>>>();

    // K4: suppression scan + output
    scan_output_kernel<<<BB, 1024>>>(out);
}